// round 12
// baseline (speedup 1.0000x reference)
#include <cuda_runtime.h>
#include <math.h>

// Problem constants (AirMPRNN: N=50000, E=1e6, T=10, H=8)
#define T_FRAMES 10
#define HID 8
#define MAXN 65536
#define MAXE 1048576

// Scratch (device globals).
__device__ float4 g_h[MAXN * 2];   // hidden: (h0..h3),(h4..h7)
__device__ float  g_v[MAXN];       // per-node edge-message scalar for current frame
__device__ float  g_agg[MAXN];     // scatter accumulator
__device__ float  g_eaT[(size_t)T_FRAMES * MAXE];  // edge_attr transposed [T][E]

struct EdgeW { const float *w1,*b1,*w2,*b2,*w3,*b3; };
struct NodeW { const float *w1,*b1,*w2,*b2,*ow1,*ob1,*ow2,*ob2; };

typedef unsigned long long u64;

__device__ __forceinline__ float sigmoidf_(float s) {
    return __fdividef(1.0f, 1.0f + __expf(-s));
}
__device__ __forceinline__ float tanhf_(float s) {
    return 1.0f - __fdividef(2.0f, __expf(2.0f * s) + 1.0f);
}

// ---- f32x2 packed helpers ----
__device__ __forceinline__ u64 pk2(float a, float b) {
    u64 r; asm("mov.b64 %0, {%1, %2};" : "=l"(r) : "f"(a), "f"(b)); return r;
}
__device__ __forceinline__ void upk2(u64 v, float& a, float& b) {
    asm("mov.b64 {%0, %1}, %2;" : "=f"(a), "=f"(b) : "l"(v));
}
__device__ __forceinline__ u64 ffma2(u64 a, u64 b, u64 c) {
    u64 d; asm("fma.rn.f32x2 %0, %1, %2, %3;" : "=l"(d) : "l"(a), "l"(b), "l"(c)); return d;
}
__device__ __forceinline__ u64 add2(u64 a, u64 b) {
    u64 d; asm("add.rn.f32x2 %0, %1, %2;" : "=l"(d) : "l"(a), "l"(b)); return d;
}
__device__ __forceinline__ u64 relu2(u64 v) {
    float a, b; upk2(v, a, b);
    return pk2(fmaxf(a, 0.f), fmaxf(b, 0.f));
}
__device__ __forceinline__ u64 shflx1_u64(u64 v) {
    unsigned lo = (unsigned)v, hi = (unsigned)(v >> 32);
    lo = __shfl_xor_sync(0xFFFFFFFFu, lo, 1);
    hi = __shfl_xor_sync(0xFFFFFFFFu, hi, 1);
    return ((u64)hi << 32) | lo;
}

// ---------------------------------------------------------------------------
// Full (single-thread) MLP1 eval — used only by init_kernel.
// ---------------------------------------------------------------------------
__device__ __forceinline__ float mlp1_eval(
    const float* in9,
    const u64* sW1p, const u64* sB1p,
    const u64* sW2p, const u64* sB2p,
    const u64* sW3p, float b3)
{
    u64 h[16];
#pragma unroll
    for (int j = 0; j < 16; j++) h[j] = sB1p[j];
#pragma unroll
    for (int k = 0; k < 9; k++) {
        u64 v = pk2(in9[k], in9[k]);
#pragma unroll
        for (int j = 0; j < 16; j++) h[j] = ffma2(v, sW1p[k * 16 + j], h[j]);
    }
#pragma unroll
    for (int j = 0; j < 16; j++) h[j] = relu2(h[j]);

    u64 acc[16];
#pragma unroll
    for (int j = 0; j < 16; j++) acc[j] = sB2p[j];
#pragma unroll
    for (int kp = 0; kp < 16; kp++) {
        float ha, hb; upk2(h[kp], ha, hb);
        u64 va = pk2(ha, ha), vb = pk2(hb, hb);
#pragma unroll
        for (int j = 0; j < 16; j++)
            acc[j] = ffma2(va, sW2p[(2 * kp) * 16 + j], acc[j]);
#pragma unroll
        for (int j = 0; j < 16; j++)
            acc[j] = ffma2(vb, sW2p[(2 * kp + 1) * 16 + j], acc[j]);
    }

    u64 s = pk2(0.f, 0.f);
#pragma unroll
    for (int j = 0; j < 16; j++) s = ffma2(relu2(acc[j]), sW3p[j], s);
    float s0, s1; upk2(s, s0, s1);
    return sigmoidf_(s0 + s1 + b3);
}

// ---------------------------------------------------------------------------
// ea transpose: [E,T] -> [T][E]. Plain launch (no PDL).
// ---------------------------------------------------------------------------
__global__ void __launch_bounds__(256) transpose_ea_kernel(
    const float* __restrict__ ea, int E)
{
    __shared__ float tile[256 * T_FRAMES];
    int base = blockIdx.x * 256;
    int cnt = min(256, E - base);
    int nflt = cnt * T_FRAMES;

    for (int i = threadIdx.x; i < nflt; i += 256)
        tile[i] = ea[(size_t)base * T_FRAMES + i];
    __syncthreads();

#pragma unroll
    for (int t = 0; t < T_FRAMES; t++) {
        if (threadIdx.x < cnt)
            g_eaT[(size_t)t * E + base + threadIdx.x] =
                tile[threadIdx.x * T_FRAMES + t];
    }
}

// ---------------------------------------------------------------------------
// Init: hidden = 0, agg = 0, v0 = sigmoid(MLP1([x0(t=0), 0..0]))
// Plain launch (no PDL attr) so edge(0)'s early phase is ordered after
// transpose completion.
// ---------------------------------------------------------------------------
__global__ void __launch_bounds__(256) init_kernel(
    const float* __restrict__ x, EdgeW W, int N)
{
    __shared__ u64 sW1[9 * 16], sB1[16], sW2[32 * 16], sB2[16], sW3[16];
    float* fW1 = (float*)sW1; float* fB1 = (float*)sB1;
    float* fW2 = (float*)sW2; float* fB2 = (float*)sB2;
    float* fW3 = (float*)sW3;
    for (int i = threadIdx.x; i < 9 * 32; i += blockDim.x)  fW1[i] = W.w1[i];
    for (int i = threadIdx.x; i < 32 * 32; i += blockDim.x) fW2[i] = W.w2[i];
    if (threadIdx.x < 32) {
        fB1[threadIdx.x] = W.b1[threadIdx.x];
        fB2[threadIdx.x] = W.b2[threadIdx.x];
        fW3[threadIdx.x] = W.w3[threadIdx.x];
    }
    __syncthreads();

    int n = blockIdx.x * blockDim.x + threadIdx.x;
    if (n >= N) return;

    float x0 = x[(size_t)n * T_FRAMES * 2 + 0];
    float in9[9] = {x0, 0.f, 0.f, 0.f, 0.f, 0.f, 0.f, 0.f, 0.f};
    g_v[n] = mlp1_eval(in9, sW1, sB1, sW2, sB2, sW3, W.b3[0]);

    g_h[n * 2 + 0] = make_float4(0.f, 0.f, 0.f, 0.f);
    g_h[n * 2 + 1] = make_float4(0.f, 0.f, 0.f, 0.f);
    g_agg[n] = 0.f;
}

// ---------------------------------------------------------------------------
// Edge scatter (PDL): pre-sync loads of ei + eaT (independent of predecessor),
// then gridsync, then v-gather + atomics. 16 edges/thread.
// ---------------------------------------------------------------------------
__global__ void __launch_bounds__(256) edge_kernel(
    const int* __restrict__ ei, int E, int t)
{
    int i = blockIdx.x * blockDim.x + threadIdx.x;
    int e0 = i * 16;
    const int* srcb = &ei[((size_t)0 * T_FRAMES + t) * (size_t)E];
    const int* dstb = &ei[((size_t)1 * T_FRAMES + t) * (size_t)E];
    const float* eab = &g_eaT[(size_t)t * E];

    if (e0 + 15 < E) {
        // ---- pre-sync phase: ei (kernel input) + eaT (written by transpose,
        // which is fully ordered before any edge launch) ----
        int4 s[4]; int4 d[4]; float4 a[4];
#pragma unroll
        for (int c = 0; c < 4; c++) {
            s[c] = *(const int4*)&srcb[e0 + 4 * c];
            d[c] = *(const int4*)&dstb[e0 + 4 * c];
            a[c] = *(const float4*)&eab[e0 + 4 * c];
        }

        cudaGridDependencySynchronize();          // wait predecessor (g_v, g_agg ready)
        cudaTriggerProgrammaticLaunchCompletion(); // let node(t) start its prologue

        float v[16];
#pragma unroll
        for (int c = 0; c < 4; c++) {
            v[4 * c + 0] = __ldg(&g_v[s[c].x]);
            v[4 * c + 1] = __ldg(&g_v[s[c].y]);
            v[4 * c + 2] = __ldg(&g_v[s[c].z]);
            v[4 * c + 3] = __ldg(&g_v[s[c].w]);
        }
#pragma unroll
        for (int c = 0; c < 4; c++) {
            atomicAdd(&g_agg[d[c].x], v[4 * c + 0] * a[c].x);
            atomicAdd(&g_agg[d[c].y], v[4 * c + 1] * a[c].y);
            atomicAdd(&g_agg[d[c].z], v[4 * c + 2] * a[c].z);
            atomicAdd(&g_agg[d[c].w], v[4 * c + 3] * a[c].w);
        }
    } else {
        cudaGridDependencySynchronize();
        cudaTriggerProgrammaticLaunchCompletion();
        for (int e = e0; e < E; e++)
            atomicAdd(&g_agg[dstb[e]], __ldg(&g_v[srcb[e]]) * eab[e]);
    }
}

// ---------------------------------------------------------------------------
// Node kernel (frame t, PDL): pre-sync weight staging + x loads, gridsync,
// then dependent reads (g_h, g_agg) and compute. TWO threads per node
// (lane q in {0,1} owns packed pairs [8q,8q+8) of 32-wide layers).
// ---------------------------------------------------------------------------
__global__ void __launch_bounds__(256) node_kernel(
    const float* __restrict__ x, NodeW W, EdgeW EW,
    float* __restrict__ out, int N, int t)
{
    // node weights (packed-j views)
    __shared__ u64 sW1[10 * 16], sB1[16], sW2[32 * 4], sB2[4];
    __shared__ u64 sO1[8 * 8], sOB1[8], sO2[8];
    // edge weights for next-frame v
    __shared__ u64 eW1[9 * 16], eB1[16], eW2[32 * 16], eB2[16], eW3[16];
    __shared__ float sOB2, eB3;

    {
        float* f;
        f = (float*)sW1; for (int i = threadIdx.x; i < 10 * 32; i += blockDim.x) f[i] = W.w1[i];
        f = (float*)sW2; for (int i = threadIdx.x; i < 32 * 8;  i += blockDim.x) f[i] = W.w2[i];
        f = (float*)sO1; for (int i = threadIdx.x; i < 8 * 16;  i += blockDim.x) f[i] = W.ow1[i];
        f = (float*)eW1; for (int i = threadIdx.x; i < 9 * 32;  i += blockDim.x) f[i] = EW.w1[i];
        f = (float*)eW2; for (int i = threadIdx.x; i < 32 * 32; i += blockDim.x) f[i] = EW.w2[i];
        if (threadIdx.x < 32) {
            ((float*)sB1)[threadIdx.x] = W.b1[threadIdx.x];
            ((float*)eB1)[threadIdx.x] = EW.b1[threadIdx.x];
            ((float*)eB2)[threadIdx.x] = EW.b2[threadIdx.x];
            ((float*)eW3)[threadIdx.x] = EW.w3[threadIdx.x];
        }
        if (threadIdx.x < 16) {
            ((float*)sOB1)[threadIdx.x] = W.ob1[threadIdx.x];
            ((float*)sO2)[threadIdx.x]  = W.ow2[threadIdx.x];
        }
        if (threadIdx.x < 8) ((float*)sB2)[threadIdx.x] = W.b2[threadIdx.x];
        if (threadIdx.x == 0) { sOB2 = W.ob2[0]; eB3 = EW.b3[0]; }
    }
    __syncthreads();

    int gid = blockIdx.x * blockDim.x + threadIdx.x;
    int n = gid >> 1;
    int q = gid & 1;
    bool valid = (n < N);
    int nc = valid ? n : (N - 1);          // clamp; no early exit (shuffles!)
    int jb = q * 8;                        // packed-pair base for 32-wide layers

    // pre-sync: x is a kernel input, safe before gridsync
    float x1  = x[(size_t)nc * T_FRAMES * 2 + (size_t)t * 2 + 1];
    float x0n = (t + 1 < T_FRAMES)
              ? x[(size_t)nc * T_FRAMES * 2 + (size_t)(t + 1) * 2 + 0] : 0.f;

    cudaGridDependencySynchronize();          // wait edge(t): g_agg complete
    cudaTriggerProgrammaticLaunchCompletion(); // let edge(t+1) pre-load ei/eaT

    float4 ha = g_h[nc * 2 + 0];
    float4 hb = g_h[nc * 2 + 1];
    float aggv = g_agg[nc];
    if (valid && q == 0) g_agg[n] = 0.f;   // reset for next frame

    float in10[10] = {x1, ha.x, ha.y, ha.z, ha.w, hb.x, hb.y, hb.z, hb.w, aggv};

    // ---- MLP2 layer1: 10 -> 32, this lane's 8 pairs ----
    u64 u[8];
#pragma unroll
    for (int j = 0; j < 8; j++) u[j] = sB1[jb + j];
#pragma unroll
    for (int k = 0; k < 10; k++) {
        u64 v = pk2(in10[k], in10[k]);
#pragma unroll
        for (int j = 0; j < 8; j++) u[j] = ffma2(v, sW1[k * 16 + jb + j], u[j]);
    }
#pragma unroll
    for (int j = 0; j < 8; j++) u[j] = relu2(u[j]);

    // ---- MLP2 layer2: 32 -> 8; partial over this lane's 16 input channels ----
    u64 a2[4];
#pragma unroll
    for (int j = 0; j < 4; j++) a2[j] = (q == 0) ? sB2[j] : pk2(0.f, 0.f);
#pragma unroll
    for (int kp = 0; kp < 8; kp++) {
        int c0 = 2 * (jb + kp);            // global input channel
        float va, vb; upk2(u[kp], va, vb);
        u64 pa = pk2(va, va), pb = pk2(vb, vb);
#pragma unroll
        for (int j = 0; j < 4; j++) a2[j] = ffma2(pa, sW2[c0 * 4 + j], a2[j]);
#pragma unroll
        for (int j = 0; j < 4; j++) a2[j] = ffma2(pb, sW2[(c0 + 1) * 4 + j], a2[j]);
    }
#pragma unroll
    for (int j = 0; j < 4; j++) a2[j] = add2(a2[j], shflx1_u64(a2[j]));

    float hn[HID];
#pragma unroll
    for (int j = 0; j < 4; j++) {
        float va, vb; upk2(a2[j], va, vb);
        hn[2 * j + 0] = tanhf_(fmaxf(va, 0.f));
        hn[2 * j + 1] = tanhf_(fmaxf(vb, 0.f));
    }

    // ---- Output head: 8 -> 16 -> 1; this lane's 4 pairs ----
    int ob4 = q * 4;
    u64 o[4];
#pragma unroll
    for (int j = 0; j < 4; j++) o[j] = sOB1[ob4 + j];
#pragma unroll
    for (int k = 0; k < 8; k++) {
        u64 v = pk2(hn[k], hn[k]);
#pragma unroll
        for (int j = 0; j < 4; j++) o[j] = ffma2(v, sO1[k * 8 + ob4 + j], o[j]);
    }
    u64 sp = pk2(0.f, 0.f);
#pragma unroll
    for (int j = 0; j < 4; j++) sp = ffma2(relu2(o[j]), sO2[ob4 + j], sp);
    float sa, sb; upk2(sp, sa, sb);
    float spart = sa + sb;
    float stot = spart + __shfl_xor_sync(0xFFFFFFFFu, spart, 1);
    if (valid && q == 0) {
        out[(size_t)t * N + n] = sigmoidf_(stot + sOB2);
        g_h[n * 2 + 0] = make_float4(hn[0], hn[1], hn[2], hn[3]);
        g_h[n * 2 + 1] = make_float4(hn[4], hn[5], hn[6], hn[7]);
    }

    // ---- MLP1 for next frame's v ----
    if (t + 1 < T_FRAMES) {
        float in9[9] = {x0n, hn[0], hn[1], hn[2], hn[3], hn[4], hn[5], hn[6], hn[7]};

        // layer1: this lane's 8 pairs
        u64 h[8];
#pragma unroll
        for (int j = 0; j < 8; j++) h[j] = eB1[jb + j];
#pragma unroll
        for (int k = 0; k < 9; k++) {
            u64 v = pk2(in9[k], in9[k]);
#pragma unroll
            for (int j = 0; j < 8; j++) h[j] = ffma2(v, eW1[k * 16 + jb + j], h[j]);
        }
#pragma unroll
        for (int j = 0; j < 8; j++) h[j] = relu2(h[j]);

        // exchange: partner's 8 pairs
        u64 hx[8];
#pragma unroll
        for (int j = 0; j < 8; j++) hx[j] = shflx1_u64(h[j]);

        // layer2: this lane's 8 output pairs over all 32 input channels
        int obp = 8 - jb;                  // partner's pair base
        u64 acc[8];
#pragma unroll
        for (int j = 0; j < 8; j++) acc[j] = eB2[jb + j];
#pragma unroll
        for (int kp = 0; kp < 8; kp++) {   // own channels
            int c0 = 2 * (jb + kp);
            float va, vb; upk2(h[kp], va, vb);
            u64 pa = pk2(va, va), pb = pk2(vb, vb);
#pragma unroll
            for (int j = 0; j < 8; j++) acc[j] = ffma2(pa, eW2[c0 * 16 + jb + j], acc[j]);
#pragma unroll
            for (int j = 0; j < 8; j++) acc[j] = ffma2(pb, eW2[(c0 + 1) * 16 + jb + j], acc[j]);
        }
#pragma unroll
        for (int kp = 0; kp < 8; kp++) {   // partner channels
            int c0 = 2 * (obp + kp);
            float va, vb; upk2(hx[kp], va, vb);
            u64 pa = pk2(va, va), pb = pk2(vb, vb);
#pragma unroll
            for (int j = 0; j < 8; j++) acc[j] = ffma2(pa, eW2[c0 * 16 + jb + j], acc[j]);
#pragma unroll
            for (int j = 0; j < 8; j++) acc[j] = ffma2(pb, eW2[(c0 + 1) * 16 + jb + j], acc[j]);
        }

        u64 vp = pk2(0.f, 0.f);
#pragma unroll
        for (int j = 0; j < 8; j++) vp = ffma2(relu2(acc[j]), eW3[jb + j], vp);
        float va, vb; upk2(vp, va, vb);
        float vpart = va + vb;
        float vtot = vpart + __shfl_xor_sync(0xFFFFFFFFu, vpart, 1);
        if (valid && q == 0) g_v[n] = sigmoidf_(vtot + eB3);
    }
}

// ---------------------------------------------------------------------------
extern "C" void kernel_launch(void* const* d_in, const int* in_sizes, int n_in,
                              void* d_out, int out_size)
{
    const float* x  = (const float*)d_in[0];
    const int*   ei = (const int*)  d_in[1];
    const float* ea = (const float*)d_in[2];

    EdgeW ew;
    ew.w1 = (const float*)d_in[3];  ew.b1 = (const float*)d_in[4];
    ew.w2 = (const float*)d_in[5];  ew.b2 = (const float*)d_in[6];
    ew.w3 = (const float*)d_in[7];  ew.b3 = (const float*)d_in[8];

    NodeW nw;
    nw.w1  = (const float*)d_in[9];  nw.b1  = (const float*)d_in[10];
    nw.w2  = (const float*)d_in[11]; nw.b2  = (const float*)d_in[12];
    nw.ow1 = (const float*)d_in[13]; nw.ob1 = (const float*)d_in[14];
    nw.ow2 = (const float*)d_in[15]; nw.ob2 = (const float*)d_in[16];

    float* out = (float*)d_out;

    int N = out_size / T_FRAMES;          // 50000
    int E = in_sizes[2] / T_FRAMES;       // 1000000

    int nb = (N + 255) / 256;
    int nb2 = (2 * N + 255) / 256;        // 2 threads per node
    int eb = ((E + 15) / 16 + 255) / 256;
    int tb = (E + 255) / 256;

    // Plain launches: transpose, then init (full stream order).
    transpose_ea_kernel<<<tb, 256>>>(ea, E);
    init_kernel<<<nb, 256>>>(x, ew, N);

    // PDL launches for the frame loop.
    cudaLaunchAttribute pdlAttr[1];
    pdlAttr[0].id = cudaLaunchAttributeProgrammaticStreamSerialization;
    pdlAttr[0].val.programmaticStreamSerializationAllowed = 1;

    for (int t = 0; t < T_FRAMES; t++) {
        {
            cudaLaunchConfig_t cfg = {};
            cfg.gridDim = dim3((unsigned)eb, 1, 1);
            cfg.blockDim = dim3(256, 1, 1);
            cfg.attrs = pdlAttr;
            cfg.numAttrs = 1;
            cudaLaunchKernelEx(&cfg, edge_kernel, ei, E, t);
        }
        {
            cudaLaunchConfig_t cfg = {};
            cfg.gridDim = dim3((unsigned)nb2, 1, 1);
            cfg.blockDim = dim3(256, 1, 1);
            cfg.attrs = pdlAttr;
            cfg.numAttrs = 1;
            cudaLaunchKernelEx(&cfg, node_kernel, x, nw, ew, out, N, t);
        }
    }
}